// round 13
// baseline (speedup 1.0000x reference)
#include <cuda_runtime.h>
#include <math.h>

#define BATCH 4
#define TSEQ 501
#define MROWS (BATCH*TSEQ)   /* 2004 */
#define DM 256
#define DI 512
#define NSTATE 16
#define NBLK 296             /* 2 CTAs/SM on 148 SMs; <=2x152 on GB300 too */

/* ---------------- persistent scratch (no allocs allowed) ---------------- */
__device__ __align__(256) float g_X    [MROWS*DM];
__device__ __align__(256) float g_TMP  [MROWS*1024];
__device__ __align__(256) float g_XC   [MROWS*DI];
__device__ __align__(256) float g_T2   [2][MROWS*1024];
__device__ __align__(256) float g_XM   [2][MROWS*DI];
__device__ __align__(256) float g_PROJ [2][MROWS*64];
__device__ __align__(256) float g_DELTA[2][MROWS*DI];
__device__ __align__(256) float g_YM   [2][MROWS*DI];
__device__ __align__(256) float g_G    [MROWS*1024];
__device__ __align__(256) float g_MU   [MROWS];
__device__ __align__(256) float g_RS   [MROWS];

/* ---------------- global barrier state ---------------- */
__device__ unsigned g_barCnt = 0;
__device__ volatile unsigned g_barSense = 0;

__device__ __forceinline__ void gsync(unsigned &sense)
{
    sense ^= 1u;                 /* every thread keeps a consistent copy */
    __threadfence();             /* make this thread's writes device-visible */
    __syncthreads();
    if (threadIdx.x == 0) {
        if (atomicAdd(&g_barCnt, 1u) == NBLK - 1u) {
            atomicExch(&g_barCnt, 0u);
            __threadfence();
            g_barSense = sense;
        } else {
            while (g_barSense != sense) __nanosleep(64);
        }
        __threadfence();
    }
    __syncthreads();
}

/* ---------------- argument bundles ---------------- */
struct GA {
    const float* A;
    const float* W;
    float*       C;
    const float* bias;
    const float* res;    /* residual add, stride ldc     */
    const float* gate;   /* silu-gate source, stride 1024 */
    const float* lnG;    /* if non-null: layernorm A rows */
    const float* lnB;
    int flipA;
    int flipC;
};

struct CA {
    const float* src;
    int          srcLd;
    const float* cw;
    const float* cb;
    float*       dst;
};

/* ---------------- patch embedding: conv1d k=10 stride=10 (own launch) ---- */
#define PPT 6
__global__ void __launch_bounds__(256) patch_kernel(const float* __restrict__ x,
                                                    const float* __restrict__ pw,
                                                    const float* __restrict__ pb)
{
    __shared__ float xs[129*PPT*10];
    __shared__ float ws[256*10];
    const int bb  = blockIdx.y;
    const int pp0 = blockIdx.x * PPT;
    const int tid = threadIdx.x;
    const int t0  = pp0 * 10;

    for (int e = tid; e < 129*PPT*10; e += 256) {
        int i   = e / (PPT*10);
        int off = e - i*(PPT*10);
        int ta  = t0 + off;
        xs[e] = (ta < 5000) ? x[((size_t)bb*129 + i)*5000 + ta] : 0.f;
    }

    const int c = tid;
    float acc[PPT];
#pragma unroll
    for (int p = 0; p < PPT; p++) acc[p] = pb[c];

    for (int i = 0; i < 129; i++) {
        __syncthreads();
        for (int e = tid; e < 2560; e += 256) {
            int cc = e / 10;
            int kk = e - cc*10;
            ws[e] = pw[(size_t)cc*1290 + i*10 + kk];
        }
        __syncthreads();
#pragma unroll
        for (int k = 0; k < 10; k++) {
            float wv = ws[c*10 + k];
            const float* xrow = &xs[i*(PPT*10) + k];
#pragma unroll
            for (int p = 0; p < PPT; p++)
                acc[p] = fmaf(wv, xrow[p*10], acc[p]);
        }
    }
#pragma unroll
    for (int p = 0; p < PPT; p++) {
        int pp = pp0 + p;
        if (pp < 500)
            g_X[((size_t)bb*TSEQ + 1 + pp)*DM + c] = acc[p];
    }
}

/* ---------------- phase: layernorm stats (mean/rstd per row) ------------- */
__device__ void ln_stats_phase()
{
    int w    = (blockIdx.x*256 + threadIdx.x) >> 5;
    int lane = threadIdx.x & 31;
    for (int row = w; row < MROWS; row += NBLK*8) {
        const float* xr = g_X + (size_t)row*DM;
        float s = 0.f, ss = 0.f;
#pragma unroll
        for (int i = 0; i < 8; i++) {
            float v = __ldcg(xr + lane + i*32);
            s += v;
            ss = fmaf(v, v, ss);
        }
#pragma unroll
        for (int o = 16; o; o >>= 1) {
            s  += __shfl_xor_sync(0xffffffffu, s,  o);
            ss += __shfl_xor_sync(0xffffffffu, ss, o);
        }
        float mean = s * (1.f/256.f);
        float var  = ss * (1.f/256.f) - mean*mean;
        if (lane == 0) {
            g_MU[row] = mean;
            g_RS[row] = rsqrtf(var + 1e-5f);
        }
    }
}

/* ---------------- phase: causal depthwise conv (K=4) + silu -------------- */
__device__ void conv_phase(CA c0a, CA c1a, int nz)
{
    int total = nz*MROWS*DI;
    for (int idx = blockIdx.x*256 + threadIdx.x; idx < total; idx += NBLK*256) {
        int z = idx / (MROWS*DI);
        int e = idx - z*(MROWS*DI);
        CA c = z ? c1a : c0a;
        int d = e & 511;
        int r = e >> 9;
        int t = r % TSEQ;
        int b = r / TSEQ;
        const float* base = c.src + ((size_t)b*TSEQ)*c.srcLd + d;
        float acc = c.cb[d];
        float w0 = c.cw[d*4+0], w1 = c.cw[d*4+1], w2 = c.cw[d*4+2], w3 = c.cw[d*4+3];
        if (t >= 3) acc = fmaf(w0, __ldcg(base + (size_t)(t-3)*c.srcLd), acc);
        if (t >= 2) acc = fmaf(w1, __ldcg(base + (size_t)(t-2)*c.srcLd), acc);
        if (t >= 1) acc = fmaf(w2, __ldcg(base + (size_t)(t-1)*c.srcLd), acc);
        acc = fmaf(w3, __ldcg(base + (size_t)t*c.srcLd), acc);
        c.dst[(size_t)r*DI + d] = acc / (1.f + __expf(-acc));
    }
}

/* ---------------- phase: GEMM 128x64 tile, 8x4/thread, grid-stride ------- */
__device__ void gemm_phase(GA ga0, GA ga1, int lda, int ldc, int K, int act,
                           int rowTiles, int colTiles, int nz,
                           float (*As)[132], float (*Bs)[68])
{
    const int tid = threadIdx.x;
    const int lr = tid >> 2;
    const int lc = (tid & 3) * 4;
    const int tx = tid & 15;
    const int ty = tid >> 4;
    const int perZ = rowTiles*colTiles;
    const int total = perZ*nz;

    for (int v = blockIdx.x; v < total; v += NBLK) {
        int z    = v / perZ;
        int rm   = v - z*perZ;
        int rowT = rm % rowTiles;
        int colT = rm / rowTiles;
        GA g = z ? ga1 : ga0;
        const int r0 = rowT*128;
        const int c0 = colT*64;

        const float* aP[2] = {nullptr, nullptr};
        float mu[2] = {0.f, 0.f}, rs[2] = {0.f, 0.f};
#pragma unroll
        for (int rr = 0; rr < 2; rr++) {
            int grow = r0 + lr + rr*64;
            if (grow < MROWS) {
                int sr = grow;
                if (g.flipA) { int bb = grow / TSEQ; int tt = grow - bb*TSEQ; sr = bb*TSEQ + (TSEQ-1-tt); }
                aP[rr] = g.A + (size_t)sr*lda + lc;
                if (g.lnG) { mu[rr] = __ldcg(g_MU + sr); rs[rr] = __ldcg(g_RS + sr); }
            }
        }
        const float* wP = g.W + (size_t)(c0 + lr)*K + lc;

        float4 pa[2], pw;
#pragma unroll
        for (int rr = 0; rr < 2; rr++)
            pa[rr] = aP[rr] ? __ldcg((const float4*)aP[rr]) : make_float4(0,0,0,0);
        pw = *(const float4*)(wP);

        float acc[8][4];
#pragma unroll
        for (int i = 0; i < 8; i++)
#pragma unroll
            for (int j = 0; j < 4; j++) acc[i][j] = 0.f;

        for (int k0 = 0; k0 < K; k0 += 16) {
            __syncthreads();
            if (g.lnG) {
                float4 g4 = *(const float4*)(g.lnG + k0 + lc);
                float4 b4 = *(const float4*)(g.lnB + k0 + lc);
#pragma unroll
                for (int rr = 0; rr < 2; rr++) {
                    As[lc+0][lr+rr*64] = (pa[rr].x - mu[rr])*rs[rr]*g4.x + b4.x;
                    As[lc+1][lr+rr*64] = (pa[rr].y - mu[rr])*rs[rr]*g4.y + b4.y;
                    As[lc+2][lr+rr*64] = (pa[rr].z - mu[rr])*rs[rr]*g4.z + b4.z;
                    As[lc+3][lr+rr*64] = (pa[rr].w - mu[rr])*rs[rr]*g4.w + b4.w;
                }
            } else {
#pragma unroll
                for (int rr = 0; rr < 2; rr++) {
                    As[lc+0][lr+rr*64] = pa[rr].x; As[lc+1][lr+rr*64] = pa[rr].y;
                    As[lc+2][lr+rr*64] = pa[rr].z; As[lc+3][lr+rr*64] = pa[rr].w;
                }
            }
            Bs[lc+0][lr] = pw.x; Bs[lc+1][lr] = pw.y;
            Bs[lc+2][lr] = pw.z; Bs[lc+3][lr] = pw.w;
            __syncthreads();
            if (k0 + 16 < K) {
#pragma unroll
                for (int rr = 0; rr < 2; rr++)
                    pa[rr] = aP[rr] ? __ldcg((const float4*)(aP[rr] + k0 + 16)) : make_float4(0,0,0,0);
                pw = *(const float4*)(wP + k0 + 16);
            }
#pragma unroll
            for (int kk = 0; kk < 16; kk++) {
                float4 a0 = *(const float4*)&As[kk][ty*8];
                float4 a1 = *(const float4*)&As[kk][ty*8+4];
                float4 b0 = *(const float4*)&Bs[kk][tx*4];
                float av[8] = {a0.x,a0.y,a0.z,a0.w,a1.x,a1.y,a1.z,a1.w};
                float bv[4] = {b0.x,b0.y,b0.z,b0.w};
#pragma unroll
                for (int i = 0; i < 8; i++)
#pragma unroll
                    for (int j = 0; j < 4; j++)
                        acc[i][j] = fmaf(av[i], bv[j], acc[i][j]);
            }
        }

#pragma unroll
        for (int i = 0; i < 8; i++) {
            int row = r0 + ty*8 + i;
            if (row >= MROWS) continue;
            int srow = row;
            if (g.flipC) { int bb = row / TSEQ; int tt = row - bb*TSEQ; srow = bb*TSEQ + (TSEQ-1-tt); }
            float* crow = g.C + (size_t)srow*ldc;
            const float* rrow = g.res  ? g.res  + (size_t)srow*ldc  : nullptr;
            const float* grow = g.gate ? g.gate + (size_t)srow*1024 : nullptr;
#pragma unroll
            for (int j = 0; j < 4; j++) {
                int col = c0 + tx*4 + j;
                float vv = acc[i][j];
                if (g.bias) vv += g.bias[col];
                if (act == 1) vv = fmaxf(vv, 0.f) + log1pf(__expf(-fabsf(vv)));
                if (grow) { float gv = __ldcg(grow + col); vv *= gv / (1.f + __expf(-gv)); }
                if (rrow) vv += __ldcg(rrow + col);
                crow[col] = vv;
            }
        }
    }
}

/* ---------------- phase: selective scan (both dirs) ---------------------- */
__device__ void scan_phase(const float* Al0, const float* Al1,
                           const float* Dp0, const float* Dp1)
{
    const int half = threadIdx.x >> 7;        /* 0/1: two 128-thread vblocks */
    const int t128 = threadIdx.x & 127;
    const int dl   = t128 >> 4;
    const int n    = t128 & 15;

    for (int v = blockIdx.x*2 + half; v < 512; v += NBLK*2) {
        int z    = v >> 8;
        int r    = v & 255;
        int b    = r >> 6;
        int dgrp = r & 63;
        int d    = dgrp*8 + dl;
        const float* Al = z ? Al1 : Al0;
        const float* Dp = z ? Dp1 : Dp0;

        const float Adn = -__expf(Al[d*NSTATE + n]);
        const float Dpd = Dp[d];
        float h = 0.f;

        const float* dptr = g_DELTA[z] + (size_t)b*TSEQ*DI + d;
        const float* uptr = g_XM[z]    + (size_t)b*TSEQ*DI + d;
        const float* pptr = g_PROJ[z]  + (size_t)b*TSEQ*64;
        const float* zptr = g_T2[z]    + (size_t)b*TSEQ*1024 + 512 + d;
        float*       yptr = g_YM[z]    + (size_t)b*TSEQ*DI + d;

        for (int t0 = 0; t0 < TSEQ; t0 += 4) {
            float dv[4], uv[4], bv[4], cv[4], zv[4];
#pragma unroll
            for (int i = 0; i < 4; i++) {
                int t = t0 + i;
                if (t < TSEQ) {
                    dv[i] = __ldcg(dptr + (size_t)t*DI);
                    uv[i] = __ldcg(uptr + (size_t)t*DI);
                    bv[i] = __ldcg(pptr + t*64 + 32 + n);
                    cv[i] = __ldcg(pptr + t*64 + 48 + n);
                    zv[i] = __ldcg(zptr + (size_t)t*1024);
                }
            }
#pragma unroll
            for (int i = 0; i < 4; i++) {
                int t = t0 + i;
                if (t < TSEQ) {
                    float dA = __expf(dv[i] * Adn);
                    h = fmaf(dA, h, dv[i] * bv[i] * uv[i]);
                    float vv = h * cv[i];
                    vv += __shfl_xor_sync(0xffffffffu, vv, 1);
                    vv += __shfl_xor_sync(0xffffffffu, vv, 2);
                    vv += __shfl_xor_sync(0xffffffffu, vv, 4);
                    vv += __shfl_xor_sync(0xffffffffu, vv, 8);
                    if (n == 0) {
                        float zz = zv[i];
                        float y = fmaf(uv[i], Dpd, vv);
                        yptr[(size_t)t*DI] = y * (zz / (1.f + __expf(-zz)));
                    }
                }
            }
        }
    }
}

/* ---------------- parameter block ---------------- */
struct Params {
    const float *cls, *ln_g, *ln_b, *in_w, *cw, *cb, *out_w, *fn_g, *fn_b;
    const float *m_in0, *m_in1, *m_cw0, *m_cw1, *m_cb0, *m_cb1;
    const float *m_xp0, *m_xp1, *m_dtw0, *m_dtw1, *m_dtb0, *m_dtb1;
    const float *m_Al0, *m_Al1, *m_D0, *m_D1, *m_ow0, *m_ow1;
    float* out;
};

/* ======================= the megakernel ======================= */
__global__ void __launch_bounds__(256, 2) mega(Params p)
{
    __shared__ float As[16][132];
    __shared__ float Bs[16][68];
    __shared__ float fs1[8], fs2[8];

    unsigned sense = g_barSense;     /* replay-safe parity init */
    const int tid = threadIdx.x;

    /* cls token write */
    if (blockIdx.x == 0) {
        for (int i = tid; i < 1024; i += 256) {
            int b = i >> 8, c = i & 255;
            g_X[((size_t)b*TSEQ)*DM + c] = p.cls[c];
        }
    }
    gsync(sense);

#pragma unroll 1
    for (int l = 0; l < 8; l++) {
        const float* lnG = p.ln_g + l*DM;
        const float* lnB = p.ln_b + l*DM;

        ln_stats_phase();
        gsync(sense);

        {   /* in-proj with fused LN on A: (2004x256)@(256x1024) -> TMP */
            GA a{g_X, p.in_w + (size_t)l*1024*DM, g_TMP,
                 nullptr, nullptr, nullptr, lnG, lnB, 0, 0};
            gemm_phase(a, a, DM, 1024, DM, 0, 16, 16, 1, As, Bs);
        }
        gsync(sense);

        {   /* conv+silu on TMP[:, :512] -> XC */
            CA c{g_TMP, 1024, p.cw + l*DI*4, p.cb + l*DI, g_XC};
            conv_phase(c, c, 1);
        }
        gsync(sense);

        {   /* mamba in-proj, both dirs -> T2[z] */
            GA a0{g_XC, p.m_in0 + (size_t)l*1024*DI, g_T2[0],
                  nullptr, nullptr, nullptr, nullptr, nullptr, 0, 0};
            GA a1{g_XC, p.m_in1 + (size_t)l*1024*DI, g_T2[1],
                  nullptr, nullptr, nullptr, nullptr, nullptr, 1, 0};
            gemm_phase(a0, a1, DI, 1024, DI, 0, 16, 16, 2, As, Bs);
        }
        gsync(sense);

        {   /* conv+silu on T2[z][:, :512] -> XM[z] */
            CA c0{g_T2[0], 1024, p.m_cw0 + l*DI*4, p.m_cb0 + l*DI, g_XM[0]};
            CA c1{g_T2[1], 1024, p.m_cw1 + l*DI*4, p.m_cb1 + l*DI, g_XM[1]};
            conv_phase(c0, c1, 2);
        }
        gsync(sense);

        {   /* x-proj -> PROJ[z] = [dt(32)|B(16)|C(16)] */
            GA a0{g_XM[0], p.m_xp0 + (size_t)l*64*DI, g_PROJ[0],
                  nullptr, nullptr, nullptr, nullptr, nullptr, 0, 0};
            GA a1{g_XM[1], p.m_xp1 + (size_t)l*64*DI, g_PROJ[1],
                  nullptr, nullptr, nullptr, nullptr, nullptr, 0, 0};
            gemm_phase(a0, a1, DI, 64, DI, 0, 16, 1, 2, As, Bs);
        }
        gsync(sense);

        {   /* dt-proj + softplus -> DELTA[z] */
            GA a0{g_PROJ[0], p.m_dtw0 + (size_t)l*DI*32, g_DELTA[0],
                  p.m_dtb0 + l*DI, nullptr, nullptr, nullptr, nullptr, 0, 0};
            GA a1{g_PROJ[1], p.m_dtw1 + (size_t)l*DI*32, g_DELTA[1],
                  p.m_dtb1 + l*DI, nullptr, nullptr, nullptr, nullptr, 0, 0};
            gemm_phase(a0, a1, 64, DI, 32, 1, 16, 8, 2, As, Bs);
        }
        gsync(sense);

        scan_phase(p.m_Al0 + (size_t)l*DI*NSTATE, p.m_Al1 + (size_t)l*DI*NSTATE,
                   p.m_D0 + l*DI, p.m_D1 + l*DI);
        gsync(sense);

        {   /* mamba out-proj + silu(res) gate -> concat G */
            GA a0{g_YM[0], p.m_ow0 + (size_t)l*DI*DI, g_G,
                  nullptr, nullptr, g_TMP + 512, nullptr, nullptr, 0, 0};
            GA a1{g_YM[1], p.m_ow1 + (size_t)l*DI*DI, g_G + 512,
                  nullptr, nullptr, g_TMP + 512, nullptr, nullptr, 0, 1};
            gemm_phase(a0, a1, DI, 1024, DI, 0, 16, 8, 2, As, Bs);
        }
        gsync(sense);

        {   /* block out-proj + residual: X = G@out_w^T + X */
            GA a{g_G, p.out_w + (size_t)l*DM*1024, g_X,
                 nullptr, g_X, nullptr, nullptr, nullptr, 0, 0};
            gemm_phase(a, a, 1024, DM, 1024, 0, 16, 4, 1, As, Bs);
        }
        gsync(sense);
    }

    /* final LN on the cls rows */
    if (blockIdx.x < BATCH) {
        int b = blockIdx.x;
        int c = tid;
        float v = __ldcg(&g_X[((size_t)b*TSEQ)*DM + c]);
        float s = v, ss = v*v;
#pragma unroll
        for (int o = 16; o; o >>= 1) {
            s  += __shfl_xor_sync(0xffffffffu, s,  o);
            ss += __shfl_xor_sync(0xffffffffu, ss, o);
        }
        int w = c >> 5, lane = c & 31;
        if (lane == 0) { fs1[w] = s; fs2[w] = ss; }
        __syncthreads();
        float ts = 0.f, tss = 0.f;
#pragma unroll
        for (int i = 0; i < 8; i++) { ts += fs1[i]; tss += fs2[i]; }
        float mean = ts * (1.f/256.f);
        float var  = tss * (1.f/256.f) - mean*mean;
        p.out[b*DM + c] = (v-mean)*rsqrtf(var + 1e-5f)*p.fn_g[c] + p.fn_b[c];
    }
}

/* ======================= host driver ======================= */
extern "C" void kernel_launch(void* const* d_in, const int* in_sizes, int n_in,
                              void* d_out, int out_size)
{
    (void)in_sizes; (void)n_in; (void)out_size;
    const float* x       = (const float*)d_in[0];
    const float* patch_w = (const float*)d_in[1];
    const float* patch_b = (const float*)d_in[2];

    Params p;
    p.cls    = (const float*)d_in[3];
    p.ln_g   = (const float*)d_in[4];
    p.ln_b   = (const float*)d_in[5];
    p.in_w   = (const float*)d_in[6];
    p.cw     = (const float*)d_in[7];
    p.cb     = (const float*)d_in[8];
    p.out_w  = (const float*)d_in[9];
    p.fn_g   = (const float*)d_in[10];
    p.fn_b   = (const float*)d_in[11];
    p.m_in0  = (const float*)d_in[12];
    p.m_cw0  = (const float*)d_in[13];
    p.m_cb0  = (const float*)d_in[14];
    p.m_xp0  = (const float*)d_in[15];
    p.m_dtw0 = (const float*)d_in[16];
    p.m_dtb0 = (const float*)d_in[17];
    p.m_Al0  = (const float*)d_in[18];
    p.m_D0   = (const float*)d_in[19];
    p.m_ow0  = (const float*)d_in[20];
    p.m_in1  = (const float*)d_in[21];
    p.m_cw1  = (const float*)d_in[22];
    p.m_cb1  = (const float*)d_in[23];
    p.m_xp1  = (const float*)d_in[24];
    p.m_dtw1 = (const float*)d_in[25];
    p.m_dtb1 = (const float*)d_in[26];
    p.m_Al1  = (const float*)d_in[27];
    p.m_D1   = (const float*)d_in[28];
    p.m_ow1  = (const float*)d_in[29];
    p.out    = (float*)d_out;

    patch_kernel<<<dim3(84, BATCH), 256>>>(x, patch_w, patch_b);
    mega<<<NBLK, 256>>>(p);
}